// round 11
// baseline (speedup 1.0000x reference)
#include <cuda_runtime.h>

// ---------------------------------------------------------------------------
// ODELayer RK4 scan, Round 11.
// Phase 1: dx_net scan. 256 CTAs x 4 rows x 512 threads, 2 CTAs per SM
//   (smem ~78.5KB/CTA, <=64 regs/thread). Independent CTAs overlap each
//   other's barriers -> sync cost off the critical path.
//   Thread = 4 cols x 1 row-pair; split-K S=8 (N=256) / S=16 (N=128),
//   all-thread parallel reduction; W1+W_lin fused; RK4 fused into W3 epilogue.
// Phase 2: out_net as big-M batched MLP (64 rows/CTA, 4096 CTAs).
// fp32 packed f32x2 FMA throughout.
// ---------------------------------------------------------------------------

#define NU   32
#define NX   128
#define NF   256
#define NIN  160
#define NT   256
#define NB   1024
#define ROWS 4
#define NPAIR (ROWS / 2)          // 2 row-pairs
#define NCTA (NB / ROWS)          // 256
#define NTHREADS 512

#define M2   64
#define P2   (M2 / 2)
#define NCTA2 ((NT * NB) / M2)    // 4096

// phase1 smem (float2): ze 320 + h1 512 + h2 512 + lin 256 + x 256 +
// pA 4096 + pB 4096 = 10048 f2 = 78.5 KB  -> 2 CTAs/SM
#define SMEM1_F2   (NPAIR*NIN + NPAIR*NF + NPAIR*NF + NPAIR*NX + NPAIR*NX + 4096 + 4096)
#define SMEM1_BYTES (SMEM1_F2 * 8)
#define SMEM2_F2   (P2*NX + P2*NF + P2*NF)
#define SMEM2_BYTES (SMEM2_F2 * 8)

__device__ float g_xhist[(size_t)NT * NB * NX];

__device__ float g_W1T[NIN * NF];
__device__ float g_WlT[NIN * NX];
__device__ float g_W2T[NF * NF];
__device__ float g_W3T[NF * NX];
__device__ float g_Wo1T[NX * NF];
__device__ float g_Wo2T[NF * NF];
__device__ float g_Wo3T[NF * NX];

using ull = unsigned long long;

__device__ __forceinline__ ull pack2(float w) {
    ull r;
    asm("mov.b64 %0, {%1, %1};" : "=l"(r) : "f"(w));
    return r;
}
__device__ __forceinline__ void fma2(ull &d, ull a, ull b) {
    asm("fma.rn.f32x2 %0, %1, %2, %0;" : "+l"(d) : "l"(a), "l"(b));
}
__device__ __forceinline__ void addf2(ull &d, ull a) {
    asm("add.rn.f32x2 %0, %0, %1;" : "+l"(d) : "l"(a));
}
__device__ __forceinline__ float2 u2f(ull v) {
    float2 r;
    asm("mov.b64 {%0, %1}, %2;" : "=f"(r.x), "=f"(r.y) : "l"(v));
    return r;
}

// ---------------------------------------------------------------------------
// Phase-1 mainloop: thread computes 4 cols x 2 row-pairs on its K/S slice.
// N=256: G=64, S=8.  N=128: G=32, S=16.  acc = 8 ull.
// ---------------------------------------------------------------------------
template <int K, int N>
__device__ __forceinline__ void mainloop(const float* __restrict__ WT,
                                         const float2* __restrict__ src,
                                         ull* acc, int tid) {
    constexpr int G  = N / 4;
    constexpr int S  = NTHREADS / G;
    constexpr int KS = K / S;
    const int cg = tid & (G - 1);
    const int kg = tid / G;
    const int n0 = cg * 4;
#pragma unroll
    for (int i = 0; i < 8; ++i) acc[i] = 0;
    const float* wp = WT + n0;
    const int kbase = kg * KS;
#pragma unroll 4
    for (int kk = 0; kk < KS; kk += 2) {
        const int k = kbase + kk;
        float4 wa = __ldg(reinterpret_cast<const float4*>(wp + (size_t)k * N));
        float4 wb = __ldg(reinterpret_cast<const float4*>(wp + (size_t)(k + 1) * N));
        ull wa0 = pack2(wa.x), wa1 = pack2(wa.y), wa2 = pack2(wa.z), wa3 = pack2(wa.w);
        ull wb0 = pack2(wb.x), wb1 = pack2(wb.y), wb2 = pack2(wb.z), wb3 = pack2(wb.w);
#pragma unroll
        for (int p = 0; p < NPAIR; ++p) {
            ulonglong2 z = *reinterpret_cast<const ulonglong2*>(src + (size_t)p * K + k);
            fma2(acc[p*4+0], z.x, wa0); fma2(acc[p*4+0], z.y, wb0);
            fma2(acc[p*4+1], z.x, wa1); fma2(acc[p*4+1], z.y, wb1);
            fma2(acc[p*4+2], z.x, wa2); fma2(acc[p*4+2], z.y, wb2);
            fma2(acc[p*4+3], z.x, wa3); fma2(acc[p*4+3], z.y, wb3);
        }
    }
}

template <int N>
__device__ __forceinline__ void store_part(float2* __restrict__ part,
                                           const ull* acc, int tid) {
    constexpr int G = N / 4;
    const int cg = tid & (G - 1);
    const int kg = tid / G;
    const int n0 = cg * 4;
    float2* pp = part + (size_t)kg * (NPAIR * N);
#pragma unroll
    for (int p = 0; p < NPAIR; ++p) {
        float2 a = u2f(acc[p*4+0]), b = u2f(acc[p*4+1]);
        float2 c = u2f(acc[p*4+2]), d = u2f(acc[p*4+3]);
        float4* q = reinterpret_cast<float4*>(pp + (size_t)p * N + n0);
        q[0] = make_float4(a.x, a.y, b.x, b.y);
        q[1] = make_float4(c.x, c.y, d.x, d.y);
    }
}

// reduce N=256 layer (8 sets of [2][256] f2): thread owns f2 element tid.
__device__ __forceinline__ void reduce256(const float2* __restrict__ part,
                                          const float* __restrict__ bias,
                                          float2* __restrict__ dst, int tid) {
    ull a0 = 0, a1 = 0;
#pragma unroll
    for (int s = 0; s < 8; s += 2) {
        addf2(a0, *reinterpret_cast<const ull*>(part + (size_t)s * (NPAIR * NF) + tid));
        addf2(a1, *reinterpret_cast<const ull*>(part + (size_t)(s + 1) * (NPAIR * NF) + tid));
    }
    addf2(a0, a1);
    const int col = tid & (NF - 1);
    float2 v = u2f(a0);
    const float c = bias[col];
    v.x = fmaxf(v.x + c, 0.f);
    v.y = fmaxf(v.y + c, 0.f);
    dst[tid] = v;
}

// reduce N=128 layer (16 sets of [2][128] f2): threads 0..255, element j=tid.
__device__ __forceinline__ float2 reduce128(const float2* __restrict__ part, int tid) {
    ull a0 = 0, a1 = 0;
#pragma unroll
    for (int s = 0; s < 16; s += 2) {
        addf2(a0, *reinterpret_cast<const ull*>(part + (size_t)s * (NPAIR * NX) + tid));
        addf2(a1, *reinterpret_cast<const ull*>(part + (size_t)(s + 1) * (NPAIR * NX) + tid));
    }
    addf2(a0, a1);
    return u2f(a0);
}

// ---------------------------------------------------------------------------
// Phase-2 layer (big-M): full-K per thread, no reduction.
// ---------------------------------------------------------------------------
template <int K, int N, bool RELU, int PPT>
__device__ __forceinline__ void layer_full(const float* __restrict__ WT,
                                           const float* __restrict__ bias,
                                           const float2* __restrict__ src,
                                           float2* __restrict__ dst,
                                           int tid) {
    constexpr int G = N / 4;
    const int cg = tid & (G - 1);
    const int pg = tid / G;
    const int p0 = pg * PPT;
    const int n0 = cg * 4;
    ull acc[PPT * 4];
#pragma unroll
    for (int i = 0; i < PPT * 4; ++i) acc[i] = 0;
    const float* wp = WT + n0;
#pragma unroll 4
    for (int k = 0; k < K; k += 2) {
        float4 wa = __ldg(reinterpret_cast<const float4*>(wp + (size_t)k * N));
        float4 wb = __ldg(reinterpret_cast<const float4*>(wp + (size_t)(k + 1) * N));
        ull wa0 = pack2(wa.x), wa1 = pack2(wa.y), wa2 = pack2(wa.z), wa3 = pack2(wa.w);
        ull wb0 = pack2(wb.x), wb1 = pack2(wb.y), wb2 = pack2(wb.z), wb3 = pack2(wb.w);
#pragma unroll
        for (int p = 0; p < PPT; ++p) {
            ulonglong2 z = *reinterpret_cast<const ulonglong2*>(src + (size_t)(p0 + p) * K + k);
            fma2(acc[p*4+0], z.x, wa0); fma2(acc[p*4+0], z.y, wb0);
            fma2(acc[p*4+1], z.x, wa1); fma2(acc[p*4+1], z.y, wb1);
            fma2(acc[p*4+2], z.x, wa2); fma2(acc[p*4+2], z.y, wb2);
            fma2(acc[p*4+3], z.x, wa3); fma2(acc[p*4+3], z.y, wb3);
        }
    }
    float4 bv = __ldg(reinterpret_cast<const float4*>(bias + n0));
#pragma unroll
    for (int p = 0; p < PPT; ++p) {
        float2 v0 = u2f(acc[p*4+0]), v1 = u2f(acc[p*4+1]);
        float2 v2 = u2f(acc[p*4+2]), v3 = u2f(acc[p*4+3]);
        v0.x += bv.x; v0.y += bv.x;
        v1.x += bv.y; v1.y += bv.y;
        v2.x += bv.z; v2.y += bv.z;
        v3.x += bv.w; v3.y += bv.w;
        if (RELU) {
            v0.x = fmaxf(v0.x, 0.f); v0.y = fmaxf(v0.y, 0.f);
            v1.x = fmaxf(v1.x, 0.f); v1.y = fmaxf(v1.y, 0.f);
            v2.x = fmaxf(v2.x, 0.f); v2.y = fmaxf(v2.y, 0.f);
            v3.x = fmaxf(v3.x, 0.f); v3.y = fmaxf(v3.y, 0.f);
        }
        float4* q = reinterpret_cast<float4*>(dst + (size_t)(p0 + p) * N + n0);
        q[0] = make_float4(v0.x, v0.y, v1.x, v1.y);
        q[1] = make_float4(v2.x, v2.y, v3.x, v3.y);
    }
}

__global__ void prep_kernel(const float* __restrict__ W_lin, const float* __restrict__ W1,
                            const float* __restrict__ W2, const float* __restrict__ W3,
                            const float* __restrict__ Wo1, const float* __restrict__ Wo2,
                            const float* __restrict__ Wo3) {
    int i0 = blockIdx.x * blockDim.x + threadIdx.x;
    int stride = gridDim.x * blockDim.x;
    for (int j = i0; j < NF * NIN; j += stride) { int n = j / NIN, k = j % NIN; g_W1T[k * NF + n] = W1[j]; }
    for (int j = i0; j < NX * NIN; j += stride) { int m = j / NIN, k = j % NIN; g_WlT[k * NX + m] = W_lin[j]; }
    for (int j = i0; j < NF * NF;  j += stride) { int n = j / NF,  k = j % NF;  g_W2T[k * NF + n] = W2[j]; }
    for (int j = i0; j < NX * NF;  j += stride) { int m = j / NF,  k = j % NF;  g_W3T[k * NX + m] = W3[j]; }
    for (int j = i0; j < NF * NX;  j += stride) { int n = j / NX,  k = j % NX;  g_Wo1T[k * NF + n] = Wo1[j]; }
    for (int j = i0; j < NF * NF;  j += stride) { int n = j / NF,  k = j % NF;  g_Wo2T[k * NF + n] = Wo2[j]; }
    for (int j = i0; j < NF * NX;  j += stride) { int m = j / NF,  k = j % NF;  g_Wo3T[k * NX + m] = Wo3[j]; }
}

// ---------------------------------------------------------------------------
// Phase 1: RK4 scan, 4 rows/CTA, 2 CTAs/SM.
// ---------------------------------------------------------------------------
__global__ void __launch_bounds__(NTHREADS, 2)
ode_kernel(const float* __restrict__ input,
           const float* __restrict__ x0,
           const float* __restrict__ dtp,
           const float* __restrict__ b1, const float* __restrict__ b2,
           const float* __restrict__ b3,
           float* __restrict__ xf_out)
{
    extern __shared__ __align__(16) char smem_raw[];
    float2* s_ze  = reinterpret_cast<float2*>(smem_raw);   // [2][NIN]
    float2* s_h1  = s_ze  + NPAIR * NIN;                   // [2][NF]
    float2* s_h2  = s_h1  + NPAIR * NF;                    // [2][NF]
    float2* s_lin = s_h2  + NPAIR * NF;                    // [2][NX]
    float2* s_x   = s_lin + NPAIR * NX;                    // [2][NX]
    float2* s_pA  = s_x   + NPAIR * NX;                    // 8 sets x 512 f2
    float2* s_pB  = s_pA  + 4096;                          // 16 sets x 256 f2

    const int tid = threadIdx.x;
    const int rowbase = blockIdx.x * ROWS;
    const float dt = *dtp;
    const float dth = 0.5f * dt;
    const float dt6 = dt * (1.0f / 6.0f);

    // load x0: 4 rows x 128 cols = 512 floats, pair-interleaved
    {
        int r = tid >> 7, c = tid & (NX - 1);
        float v = x0[(size_t)(rowbase + r) * NX + c];
        ((float*)&s_x[(r >> 1) * NX + c])[r & 1] = v;
    }
    __syncthreads();

    ull acc[8];
    const int zp = tid >> 7, zc = tid & (NX - 1);  // for tid<256: [2][128] slot

    for (int t = 0; t < NT; ++t) {
        // setup: u -> tail of z (4 rows x 32), x -> head of z
        if (tid < ROWS * NU) {
            int r = tid >> 5, c = tid & 31;
            float v = input[((size_t)t * NB + rowbase + r) * NU + c];
            ((float*)&s_ze[(r >> 1) * NIN + NX + c])[r & 1] = v;
        }
        if (tid < NPAIR * NX) {
            s_ze[zp * NIN + zc] = s_x[tid];
        }
        __syncthreads();

        float2 ks = make_float2(0.f, 0.f);

#pragma unroll 1
        for (int e = 0; e < 4; ++e) {
            // fused W1 + W_lin (both read s_ze)
            mainloop<NIN, NF>(g_W1T, s_ze, acc, tid);
            store_part<NF>(s_pA, acc, tid);
            mainloop<NIN, NX>(g_WlT, s_ze, acc, tid);
            store_part<NX>(s_pB, acc, tid);
            __syncthreads();
            reduce256(s_pA, b1, s_h1, tid);
            if (tid < NPAIR * NX) s_lin[tid] = reduce128(s_pB, tid);
            __syncthreads();

            // W2
            mainloop<NF, NF>(g_W2T, s_h1, acc, tid);
            store_part<NF>(s_pA, acc, tid);
            __syncthreads();
            reduce256(s_pA, b2, s_h2, tid);
            __syncthreads();

            // W3 + fused RK4 epilogue
            mainloop<NF, NX>(g_W3T, s_h2, acc, tid);
            store_part<NX>(s_pB, acc, tid);
            __syncthreads();
            if (tid < NPAIR * NX) {
                float2 kv = reduce128(s_pB, tid);
                const float bb = b3[zc];
                float2 lv = s_lin[tid];
                kv.x += lv.x + bb;
                kv.y += lv.y + bb;
                float2 xv = s_x[tid];
                if (e == 0) {
                    ks = kv;
                    s_ze[zp * NIN + zc] = make_float2(fmaf(dth, kv.x, xv.x),
                                                      fmaf(dth, kv.y, xv.y));
                } else if (e == 1) {
                    ks.x = fmaf(2.f, kv.x, ks.x); ks.y = fmaf(2.f, kv.y, ks.y);
                    s_ze[zp * NIN + zc] = make_float2(fmaf(dth, kv.x, xv.x),
                                                      fmaf(dth, kv.y, xv.y));
                } else if (e == 2) {
                    ks.x = fmaf(2.f, kv.x, ks.x); ks.y = fmaf(2.f, kv.y, ks.y);
                    s_ze[zp * NIN + zc] = make_float2(fmaf(dt, kv.x, xv.x),
                                                      fmaf(dt, kv.y, xv.y));
                } else {
                    ks.x += kv.x; ks.y += kv.y;
                    s_x[tid] = make_float2(fmaf(dt6, ks.x, xv.x),
                                           fmaf(dt6, ks.y, xv.y));
                }
            }
            __syncthreads();
        }

        // store x_{t+1} history (512 floats, coalesced)
        {
            int r = tid >> 7, c = tid & (NX - 1);
            float v = ((const float*)&s_x[(r >> 1) * NX + c])[r & 1];
            g_xhist[((size_t)t * NB + rowbase + r) * NX + c] = v;
        }
    }

    __syncthreads();
    {
        int r = tid >> 7, c = tid & (NX - 1);
        xf_out[(size_t)(rowbase + r) * NX + c] =
            ((const float*)&s_x[(r >> 1) * NX + c])[r & 1];
    }
}

// ---------------------------------------------------------------------------
// Phase 2: out_net over all NT*NB rows, 64 rows per CTA.
// ---------------------------------------------------------------------------
__global__ void __launch_bounds__(NTHREADS, 1)
out_kernel(const float* __restrict__ bo1, const float* __restrict__ bo2,
           const float* __restrict__ bo3,
           float* __restrict__ y_out)
{
    extern __shared__ __align__(16) char smem_raw[];
    float2* s_x  = reinterpret_cast<float2*>(smem_raw);  // [P2][NX]
    float2* s_h1 = s_x  + P2 * NX;                       // [P2][NF]
    float2* s_h2 = s_h1 + P2 * NF;                       // [P2][NF]

    const int tid = threadIdx.x;
    const size_t R0 = (size_t)blockIdx.x * M2;

    for (int idx = tid; idx < M2 * NX; idx += NTHREADS) {
        int r = idx >> 7, c = idx & (NX - 1);
        float v = g_xhist[(R0 + r) * NX + c];
        ((float*)&s_x[(r >> 1) * NX + c])[r & 1] = v;
    }
    __syncthreads();

    layer_full<NX, NF, true, 4>(g_Wo1T, bo1, s_x, s_h1, tid);
    __syncthreads();
    layer_full<NF, NF, true, 4>(g_Wo2T, bo2, s_h1, s_h2, tid);
    __syncthreads();
    layer_full<NF, NX, false, 2>(g_Wo3T, bo3, s_h2, s_x, tid);
    __syncthreads();

    for (int idx = tid; idx < M2 * NX; idx += NTHREADS) {
        int r = idx >> 7, c = idx & (NX - 1);
        y_out[(R0 + r) * NX + c] =
            ((const float*)&s_x[(r >> 1) * NX + c])[r & 1];
    }
}

extern "C" void kernel_launch(void* const* d_in, const int* in_sizes, int n_in,
                              void* d_out, int out_size) {
    const float* input = (const float*)d_in[0];
    const float* x_step = (const float*)d_in[1];
    const float* dtp   = (const float*)d_in[2];
    const float* W_lin = (const float*)d_in[3];
    const float* W1    = (const float*)d_in[4];
    const float* b1    = (const float*)d_in[5];
    const float* W2    = (const float*)d_in[6];
    const float* b2    = (const float*)d_in[7];
    const float* W3    = (const float*)d_in[8];
    const float* b3    = (const float*)d_in[9];
    const float* Wo1   = (const float*)d_in[10];
    const float* bo1   = (const float*)d_in[11];
    const float* Wo2   = (const float*)d_in[12];
    const float* bo2   = (const float*)d_in[13];
    const float* Wo3   = (const float*)d_in[14];
    const float* bo3   = (const float*)d_in[15];

    float* out = (float*)d_out;
    float* y_out  = out;
    float* xf_out = out + (size_t)NT * NB * NX;

    static bool attr_done = false;
    if (!attr_done) {
        cudaFuncSetAttribute(ode_kernel,
                             cudaFuncAttributeMaxDynamicSharedMemorySize,
                             SMEM1_BYTES);
        cudaFuncSetAttribute(out_kernel,
                             cudaFuncAttributeMaxDynamicSharedMemorySize,
                             SMEM2_BYTES);
        attr_done = true;
    }

    prep_kernel<<<256, 256>>>(W_lin, W1, W2, W3, Wo1, Wo2, Wo3);
    ode_kernel<<<NCTA, NTHREADS, SMEM1_BYTES>>>(input, x_step, dtp,
                                                b1, b2, b3, xf_out);
    out_kernel<<<NCTA2, NTHREADS, SMEM2_BYTES>>>(bo1, bo2, bo3, y_out);
}

// round 13
// speedup vs baseline: 1.0949x; 1.0949x over previous
#include <cuda_runtime.h>
#include <cuda_fp16.h>

// ---------------------------------------------------------------------------
// ODELayer RK4 scan, Round 12.
// Structure = R9 (best): 128 CTAs x 8 rows x 512 thr, 1 CTA/SM.
//   dx_net scan with split-K + all-thread parallel reduction, W1+Wl fused,
//   RK4 fused into W3 epilogue. Phase 2: big-M out_net (64 rows/CTA).
// NEW: weights stored as fp16 (halve weight L1 traffic, the measured binder;
//   R11 showed doubling weight traffic cost ~+13k cyc/step -> halving it
//   should save ~12k). Activations/accumulators/state stay fp32.
// ---------------------------------------------------------------------------

#define NU   32
#define NX   128
#define NF   256
#define NIN  160
#define NT   256
#define NB   1024
#define ROWS 8
#define NCTA (NB / ROWS)   // 128
#define NTHREADS 512

#define M2   64
#define P2   (M2 / 2)
#define NCTA2 ((NT * NB) / M2)   // 4096

#define SMEM1_F2   (4*NIN + 4*NF + 4*NF + 4*NX + 4*NX + 8192 + 8192)
#define SMEM1_BYTES (SMEM1_F2 * 8)
#define SMEM2_F2   (P2*NX + P2*NF + P2*NF)
#define SMEM2_BYTES (SMEM2_F2 * 8)

__device__ float g_xhist[(size_t)NT * NB * NX];

// fp16 transposed weights [K][N]
__device__ __half g_W1H[NIN * NF];
__device__ __half g_WlH[NIN * NX];
__device__ __half g_W2H[NF * NF];
__device__ __half g_W3H[NF * NX];
__device__ __half g_Wo1H[NX * NF];
__device__ __half g_Wo2H[NF * NF];
__device__ __half g_Wo3H[NF * NX];

using ull = unsigned long long;

__device__ __forceinline__ ull pack2(float w) {
    ull r;
    asm("mov.b64 %0, {%1, %1};" : "=l"(r) : "f"(w));
    return r;
}
__device__ __forceinline__ void fma2(ull &d, ull a, ull b) {
    asm("fma.rn.f32x2 %0, %1, %2, %0;" : "+l"(d) : "l"(a), "l"(b));
}
__device__ __forceinline__ void addf2(ull &d, ull a) {
    asm("add.rn.f32x2 %0, %0, %1;" : "+l"(d) : "l"(a));
}
__device__ __forceinline__ float2 u2f(ull v) {
    float2 r;
    asm("mov.b64 {%0, %1}, %2;" : "=f"(r.x), "=f"(r.y) : "l"(v));
    return r;
}
// 4 fp16 weights (8B) -> 4 duplicated f32x2 registers
__device__ __forceinline__ void unpack_w4(uint2 h, ull &w0, ull &w1, ull &w2, ull &w3) {
    float2 f01 = __half22float2(*reinterpret_cast<__half2*>(&h.x));
    float2 f23 = __half22float2(*reinterpret_cast<__half2*>(&h.y));
    w0 = pack2(f01.x); w1 = pack2(f01.y);
    w2 = pack2(f23.x); w3 = pack2(f23.y);
}

// ---------------------------------------------------------------------------
// Phase-1 mainloop: thread computes 4 cols x 4 row-pairs on its K/S slice.
// N=256: G=64, S=8.  N=128: G=32, S=16.
// ---------------------------------------------------------------------------
template <int K, int N>
__device__ __forceinline__ void mainloop(const __half* __restrict__ WH,
                                         const float2* __restrict__ src,
                                         ull* acc, int tid) {
    constexpr int G  = N / 4;
    constexpr int S  = NTHREADS / G;
    constexpr int KS = K / S;
    const int cg = tid & (G - 1);
    const int kg = tid / G;
    const int n0 = cg * 4;
#pragma unroll
    for (int i = 0; i < 16; ++i) acc[i] = 0;
    const __half* wp = WH + n0;
    const int kbase = kg * KS;
#pragma unroll 8
    for (int kk = 0; kk < KS; kk += 2) {
        const int k = kbase + kk;
        uint2 ha = __ldg(reinterpret_cast<const uint2*>(wp + (size_t)k * N));
        uint2 hb = __ldg(reinterpret_cast<const uint2*>(wp + (size_t)(k + 1) * N));
        ull wa0, wa1, wa2, wa3, wb0, wb1, wb2, wb3;
        unpack_w4(ha, wa0, wa1, wa2, wa3);
        unpack_w4(hb, wb0, wb1, wb2, wb3);
#pragma unroll
        for (int p = 0; p < 4; ++p) {
            ulonglong2 z = *reinterpret_cast<const ulonglong2*>(src + (size_t)p * K + k);
            fma2(acc[p*4+0], z.x, wa0); fma2(acc[p*4+0], z.y, wb0);
            fma2(acc[p*4+1], z.x, wa1); fma2(acc[p*4+1], z.y, wb1);
            fma2(acc[p*4+2], z.x, wa2); fma2(acc[p*4+2], z.y, wb2);
            fma2(acc[p*4+3], z.x, wa3); fma2(acc[p*4+3], z.y, wb3);
        }
    }
}

template <int N>
__device__ __forceinline__ void store_part(float2* __restrict__ part,
                                           const ull* acc, int tid) {
    constexpr int G = N / 4;
    const int cg = tid & (G - 1);
    const int kg = tid / G;
    const int n0 = cg * 4;
    float2* pp = part + (size_t)kg * (4 * N);
#pragma unroll
    for (int p = 0; p < 4; ++p) {
        float2 a = u2f(acc[p*4+0]), b = u2f(acc[p*4+1]);
        float2 c = u2f(acc[p*4+2]), d = u2f(acc[p*4+3]);
        float4* q = reinterpret_cast<float4*>(pp + (size_t)p * N + n0);
        q[0] = make_float4(a.x, a.y, b.x, b.y);
        q[1] = make_float4(c.x, c.y, d.x, d.y);
    }
}

// reduce one N=256 layer: thread owns f2 elements {2*tid, 2*tid+1} of [4][256]
__device__ __forceinline__ void reduce256(const float2* __restrict__ part,  // 8 sets
                                          const float* __restrict__ bias,
                                          float2* __restrict__ dst, int tid) {
    const int j = 2 * tid;
    ull a0 = 0, a1 = 0, b0 = 0, b1 = 0;
#pragma unroll
    for (int s = 0; s < 8; s += 2) {
        ulonglong2 qa = *reinterpret_cast<const ulonglong2*>(part + (size_t)s * 1024 + j);
        ulonglong2 qb = *reinterpret_cast<const ulonglong2*>(part + (size_t)(s + 1) * 1024 + j);
        addf2(a0, qa.x); addf2(a1, qa.y);
        addf2(b0, qb.x); addf2(b1, qb.y);
    }
    addf2(a0, b0); addf2(a1, b1);
    const int col = j & (NF - 1);
    float2 v0 = u2f(a0), v1 = u2f(a1);
    float c0 = bias[col], c1 = bias[col + 1];
    v0.x = fmaxf(v0.x + c0, 0.f); v0.y = fmaxf(v0.y + c0, 0.f);
    v1.x = fmaxf(v1.x + c1, 0.f); v1.y = fmaxf(v1.y + c1, 0.f);
    *reinterpret_cast<float4*>(dst + j) = make_float4(v0.x, v0.y, v1.x, v1.y);
}

// reduce one N=128 layer (16 sets): thread's f2 element (index tid of [4][128])
__device__ __forceinline__ float2 reduce128(const float2* __restrict__ part, int tid) {
    ull a0 = 0, a1 = 0;
#pragma unroll
    for (int s = 0; s < 16; s += 2) {
        addf2(a0, *reinterpret_cast<const ull*>(part + (size_t)s * 512 + tid));
        addf2(a1, *reinterpret_cast<const ull*>(part + (size_t)(s + 1) * 512 + tid));
    }
    addf2(a0, a1);
    return u2f(a0);
}

// ---------------------------------------------------------------------------
// Phase-2 layer (big-M): full-K per thread, no reduction. fp16 weights.
// ---------------------------------------------------------------------------
template <int K, int N, bool RELU, int PPT>
__device__ __forceinline__ void layer_full(const __half* __restrict__ WH,
                                           const float* __restrict__ bias,
                                           const float2* __restrict__ src,
                                           float2* __restrict__ dst,
                                           int tid) {
    constexpr int G = N / 4;
    const int cg = tid & (G - 1);
    const int pg = tid / G;
    const int p0 = pg * PPT;
    const int n0 = cg * 4;
    ull acc[PPT * 4];
#pragma unroll
    for (int i = 0; i < PPT * 4; ++i) acc[i] = 0;
    const __half* wp = WH + n0;
#pragma unroll 4
    for (int k = 0; k < K; k += 2) {
        uint2 ha = __ldg(reinterpret_cast<const uint2*>(wp + (size_t)k * N));
        uint2 hb = __ldg(reinterpret_cast<const uint2*>(wp + (size_t)(k + 1) * N));
        ull wa0, wa1, wa2, wa3, wb0, wb1, wb2, wb3;
        unpack_w4(ha, wa0, wa1, wa2, wa3);
        unpack_w4(hb, wb0, wb1, wb2, wb3);
#pragma unroll
        for (int p = 0; p < PPT; ++p) {
            ulonglong2 z = *reinterpret_cast<const ulonglong2*>(src + (size_t)(p0 + p) * K + k);
            fma2(acc[p*4+0], z.x, wa0); fma2(acc[p*4+0], z.y, wb0);
            fma2(acc[p*4+1], z.x, wa1); fma2(acc[p*4+1], z.y, wb1);
            fma2(acc[p*4+2], z.x, wa2); fma2(acc[p*4+2], z.y, wb2);
            fma2(acc[p*4+3], z.x, wa3); fma2(acc[p*4+3], z.y, wb3);
        }
    }
    float4 bv = __ldg(reinterpret_cast<const float4*>(bias + n0));
#pragma unroll
    for (int p = 0; p < PPT; ++p) {
        float2 v0 = u2f(acc[p*4+0]), v1 = u2f(acc[p*4+1]);
        float2 v2 = u2f(acc[p*4+2]), v3 = u2f(acc[p*4+3]);
        v0.x += bv.x; v0.y += bv.x;
        v1.x += bv.y; v1.y += bv.y;
        v2.x += bv.z; v2.y += bv.z;
        v3.x += bv.w; v3.y += bv.w;
        if (RELU) {
            v0.x = fmaxf(v0.x, 0.f); v0.y = fmaxf(v0.y, 0.f);
            v1.x = fmaxf(v1.x, 0.f); v1.y = fmaxf(v1.y, 0.f);
            v2.x = fmaxf(v2.x, 0.f); v2.y = fmaxf(v2.y, 0.f);
            v3.x = fmaxf(v3.x, 0.f); v3.y = fmaxf(v3.y, 0.f);
        }
        float4* q = reinterpret_cast<float4*>(dst + (size_t)(p0 + p) * N + n0);
        q[0] = make_float4(v0.x, v0.y, v1.x, v1.y);
        q[1] = make_float4(v2.x, v2.y, v3.x, v3.y);
    }
}

__global__ void prep_kernel(const float* __restrict__ W_lin, const float* __restrict__ W1,
                            const float* __restrict__ W2, const float* __restrict__ W3,
                            const float* __restrict__ Wo1, const float* __restrict__ Wo2,
                            const float* __restrict__ Wo3) {
    int i0 = blockIdx.x * blockDim.x + threadIdx.x;
    int stride = gridDim.x * blockDim.x;
    for (int j = i0; j < NF * NIN; j += stride) { int n = j / NIN, k = j % NIN; g_W1H[k * NF + n] = __float2half_rn(W1[j]); }
    for (int j = i0; j < NX * NIN; j += stride) { int m = j / NIN, k = j % NIN; g_WlH[k * NX + m] = __float2half_rn(W_lin[j]); }
    for (int j = i0; j < NF * NF;  j += stride) { int n = j / NF,  k = j % NF;  g_W2H[k * NF + n] = __float2half_rn(W2[j]); }
    for (int j = i0; j < NX * NF;  j += stride) { int m = j / NF,  k = j % NF;  g_W3H[k * NX + m] = __float2half_rn(W3[j]); }
    for (int j = i0; j < NF * NX;  j += stride) { int n = j / NX,  k = j % NX;  g_Wo1H[k * NF + n] = __float2half_rn(Wo1[j]); }
    for (int j = i0; j < NF * NF;  j += stride) { int n = j / NF,  k = j % NF;  g_Wo2H[k * NF + n] = __float2half_rn(Wo2[j]); }
    for (int j = i0; j < NF * NX;  j += stride) { int m = j / NF,  k = j % NF;  g_Wo3H[k * NX + m] = __float2half_rn(Wo3[j]); }
}

// ---------------------------------------------------------------------------
// Phase 1
// ---------------------------------------------------------------------------
__global__ void __launch_bounds__(NTHREADS, 1)
ode_kernel(const float* __restrict__ input,
           const float* __restrict__ x0,
           const float* __restrict__ dtp,
           const float* __restrict__ b1, const float* __restrict__ b2,
           const float* __restrict__ b3,
           float* __restrict__ xf_out)
{
    extern __shared__ __align__(16) char smem_raw[];
    float2* s_ze  = reinterpret_cast<float2*>(smem_raw);  // [4][NIN]
    float2* s_h1  = s_ze  + 4 * NIN;                      // [4][NF]
    float2* s_h2  = s_h1  + 4 * NF;                       // [4][NF]
    float2* s_lin = s_h2  + 4 * NF;                       // [4][NX]
    float2* s_x   = s_lin + 4 * NX;                       // [4][NX]
    float2* s_pA  = s_x   + 4 * NX;                       // 8 sets x 1024 f2
    float2* s_pB  = s_pA  + 8192;                         // 16 sets x 512 f2

    const int tid = threadIdx.x;
    const int rowbase = blockIdx.x * ROWS;
    const float dt = *dtp;
    const float dth = 0.5f * dt;
    const float dt6 = dt * (1.0f / 6.0f);

    for (int idx = tid; idx < ROWS * NX; idx += NTHREADS) {
        int r = idx >> 7, c = idx & (NX - 1);
        float v = x0[(size_t)(rowbase + r) * NX + c];
        ((float*)&s_x[(r >> 1) * NX + c])[r & 1] = v;
    }
    __syncthreads();

    ull acc[16];
    const int zp = tid >> 7, zc = tid & (NX - 1);

    for (int t = 0; t < NT; ++t) {
        if (tid < ROWS * NU) {
            int r = tid >> 5, c = tid & 31;
            float v = input[((size_t)t * NB + rowbase + r) * NU + c];
            ((float*)&s_ze[(r >> 1) * NIN + NX + c])[r & 1] = v;
        }
        s_ze[zp * NIN + zc] = s_x[tid];
        __syncthreads();

        float2 ks = make_float2(0.f, 0.f);

#pragma unroll 1
        for (int e = 0; e < 4; ++e) {
            // fused W1 + W_lin
            mainloop<NIN, NF>(g_W1H, s_ze, acc, tid);
            store_part<NF>(s_pA, acc, tid);
            mainloop<NIN, NX>(g_WlH, s_ze, acc, tid);
            store_part<NX>(s_pB, acc, tid);
            __syncthreads();
            reduce256(s_pA, b1, s_h1, tid);
            s_lin[tid] = reduce128(s_pB, tid);
            __syncthreads();

            // W2
            mainloop<NF, NF>(g_W2H, s_h1, acc, tid);
            store_part<NF>(s_pA, acc, tid);
            __syncthreads();
            reduce256(s_pA, b2, s_h2, tid);
            __syncthreads();

            // W3 + fused RK4 epilogue
            mainloop<NF, NX>(g_W3H, s_h2, acc, tid);
            store_part<NX>(s_pB, acc, tid);
            __syncthreads();
            {
                float2 kv = reduce128(s_pB, tid);
                const float bb = b3[zc];
                float2 lv = s_lin[tid];
                kv.x += lv.x + bb;
                kv.y += lv.y + bb;
                float2 xv = s_x[tid];
                if (e == 0) {
                    ks = kv;
                    s_ze[zp * NIN + zc] = make_float2(fmaf(dth, kv.x, xv.x),
                                                      fmaf(dth, kv.y, xv.y));
                } else if (e == 1) {
                    ks.x = fmaf(2.f, kv.x, ks.x); ks.y = fmaf(2.f, kv.y, ks.y);
                    s_ze[zp * NIN + zc] = make_float2(fmaf(dth, kv.x, xv.x),
                                                      fmaf(dth, kv.y, xv.y));
                } else if (e == 2) {
                    ks.x = fmaf(2.f, kv.x, ks.x); ks.y = fmaf(2.f, kv.y, ks.y);
                    s_ze[zp * NIN + zc] = make_float2(fmaf(dt, kv.x, xv.x),
                                                      fmaf(dt, kv.y, xv.y));
                } else {
                    ks.x += kv.x; ks.y += kv.y;
                    s_x[tid] = make_float2(fmaf(dt6, ks.x, xv.x),
                                           fmaf(dt6, ks.y, xv.y));
                }
            }
            __syncthreads();
        }

        // store x_{t+1} history (coalesced)
        for (int idx = tid; idx < ROWS * NX; idx += NTHREADS) {
            int r = idx >> 7, c = idx & (NX - 1);
            float v = ((const float*)&s_x[(r >> 1) * NX + c])[r & 1];
            g_xhist[((size_t)t * NB + rowbase + r) * NX + c] = v;
        }
    }

    __syncthreads();
    for (int idx = tid; idx < ROWS * NX; idx += NTHREADS) {
        int r = idx >> 7, c = idx & (NX - 1);
        xf_out[(size_t)(rowbase + r) * NX + c] =
            ((const float*)&s_x[(r >> 1) * NX + c])[r & 1];
    }
}

// ---------------------------------------------------------------------------
// Phase 2
// ---------------------------------------------------------------------------
__global__ void __launch_bounds__(NTHREADS, 1)
out_kernel(const float* __restrict__ bo1, const float* __restrict__ bo2,
           const float* __restrict__ bo3,
           float* __restrict__ y_out)
{
    extern __shared__ __align__(16) char smem_raw[];
    float2* s_x  = reinterpret_cast<float2*>(smem_raw);  // [P2][NX]
    float2* s_h1 = s_x  + P2 * NX;                       // [P2][NF]
    float2* s_h2 = s_h1 + P2 * NF;                       // [P2][NF]

    const int tid = threadIdx.x;
    const size_t R0 = (size_t)blockIdx.x * M2;

    for (int idx = tid; idx < M2 * NX; idx += NTHREADS) {
        int r = idx >> 7, c = idx & (NX - 1);
        float v = g_xhist[(R0 + r) * NX + c];
        ((float*)&s_x[(r >> 1) * NX + c])[r & 1] = v;
    }
    __syncthreads();

    layer_full<NX, NF, true, 4>(g_Wo1H, bo1, s_x, s_h1, tid);
    __syncthreads();
    layer_full<NF, NF, true, 4>(g_Wo2H, bo2, s_h1, s_h2, tid);
    __syncthreads();
    layer_full<NF, NX, false, 2>(g_Wo3H, bo3, s_h2, s_x, tid);
    __syncthreads();

    for (int idx = tid; idx < M2 * NX; idx += NTHREADS) {
        int r = idx >> 7, c = idx & (NX - 1);
        y_out[(R0 + r) * NX + c] =
            ((const float*)&s_x[(r >> 1) * NX + c])[r & 1];
    }
}

extern "C" void kernel_launch(void* const* d_in, const int* in_sizes, int n_in,
                              void* d_out, int out_size) {
    const float* input = (const float*)d_in[0];
    const float* x_step = (const float*)d_in[1];
    const float* dtp   = (const float*)d_in[2];
    const float* W_lin = (const float*)d_in[3];
    const float* W1    = (const float*)d_in[4];
    const float* b1    = (const float*)d_in[5];
    const float* W2    = (const float*)d_in[6];
    const float* b2    = (const float*)d_in[7];
    const float* W3    = (const float*)d_in[8];
    const float* b3    = (const float*)d_in[9];
    const float* Wo1   = (const float*)d_in[10];
    const float* bo1   = (const float*)d_in[11];
    const float* Wo2   = (const float*)d_in[12];
    const float* bo2   = (const float*)d_in[13];
    const float* Wo3   = (const float*)d_in[14];
    const float* bo3   = (const float*)d_in[15];

    float* out = (float*)d_out;
    float* y_out  = out;
    float* xf_out = out + (size_t)NT * NB * NX;

    static bool attr_done = false;
    if (!attr_done) {
        cudaFuncSetAttribute(ode_kernel,
                             cudaFuncAttributeMaxDynamicSharedMemorySize,
                             SMEM1_BYTES);
        cudaFuncSetAttribute(out_kernel,
                             cudaFuncAttributeMaxDynamicSharedMemorySize,
                             SMEM2_BYTES);
        attr_done = true;
    }

    prep_kernel<<<256, 256>>>(W_lin, W1, W2, W3, Wo1, Wo2, Wo3);
    ode_kernel<<<NCTA, NTHREADS, SMEM1_BYTES>>>(input, x_step, dtp,
                                                b1, b2, b3, xf_out);
    out_kernel<<<NCTA2, NTHREADS, SMEM2_BYTES>>>(bo1, bo2, bo3, y_out);
}